// round 1
// baseline (speedup 1.0000x reference)
#include <cuda_runtime.h>

// IoULoss: loss = mean_i ( 1 - IoU(pred_i, target_i) )
// Reference builds an NxN IoU matrix but only uses the diagonal -> O(N) work.
// N = 8192, inputs are (N,4) float32 center-format boxes [cx, cy, w, h].
// Output: single float32 scalar.

#define EPS 1e-7f

__global__ __launch_bounds__(1024, 1)
void iou_loss_kernel(const float4* __restrict__ pred,
                     const float4* __restrict__ targ,
                     float* __restrict__ out,
                     int n)
{
    float sum = 0.0f;

    // grid = 1 block; grid-stride over pairs (8 iters/thread at N=8192).
    for (int i = threadIdx.x; i < n; i += blockDim.x) {
        float4 a = __ldg(&pred[i]);   // cx, cy, w, h
        float4 b = __ldg(&targ[i]);

        // Corner form — match reference rounding behavior.
        float ax1 = a.x - a.z * 0.5f;
        float ay1 = a.y - a.w * 0.5f;
        float ax2 = a.x + a.z * 0.5f;
        float ay2 = a.y + a.w * 0.5f;

        float bx1 = b.x - b.z * 0.5f;
        float by1 = b.y - b.w * 0.5f;
        float bx2 = b.x + b.z * 0.5f;
        float by2 = b.y + b.w * 0.5f;

        float iw = fminf(ax2, bx2) - fmaxf(ax1, bx1);
        float ih = fminf(ay2, by2) - fmaxf(ay1, by1);
        iw = fmaxf(iw, 0.0f);
        ih = fmaxf(ih, 0.0f);
        float inter = iw * ih;

        float area1 = (ax2 - ax1) * (ay2 - ay1);
        float area2 = (bx2 - bx1) * (by2 - by1);
        float uni   = area1 + area2 - inter;

        sum += 1.0f - inter / (uni + EPS);
    }

    // Intra-warp reduce.
    #pragma unroll
    for (int off = 16; off > 0; off >>= 1)
        sum += __shfl_xor_sync(0xFFFFFFFFu, sum, off);

    // Cross-warp reduce via smem.
    __shared__ float warp_sums[32];
    int lane = threadIdx.x & 31;
    int wid  = threadIdx.x >> 5;
    if (lane == 0) warp_sums[wid] = sum;
    __syncthreads();

    if (wid == 0) {
        int nwarps = (blockDim.x + 31) >> 5;
        float v = (lane < nwarps) ? warp_sums[lane] : 0.0f;
        #pragma unroll
        for (int off = 16; off > 0; off >>= 1)
            v += __shfl_xor_sync(0xFFFFFFFFu, v, off);
        if (lane == 0)
            out[0] = v / (float)n;
    }
}

extern "C" void kernel_launch(void* const* d_in, const int* in_sizes, int n_in,
                              void* d_out, int out_size)
{
    const float4* pred = (const float4*)d_in[0];  // pred_boxes  (N,4) f32
    const float4* targ = (const float4*)d_in[1];  // target_boxes (N,4) f32
    float* out = (float*)d_out;                   // scalar f32

    int n = in_sizes[0] / 4;                      // number of boxes

    iou_loss_kernel<<<1, 1024>>>(pred, targ, out, n);
}

// round 4
// speedup vs baseline: 1.2605x; 1.2605x over previous
#include <cuda_runtime.h>

// IoULoss: loss = mean_i ( 1 - IoU(pred_i, target_i) )   (diagonal-only, O(N))
// N = 8192 boxes, (N,4) f32 center-format [cx,cy,w,h]. Output: 1 f32 scalar.
//
// Strategy: one pair per thread, single wave across the chip (128 blocks x 64
// threads -> one CTA per SM on 128 SMs), so all DRAM latency is paid once and
// the L1tex queues are shallow everywhere. Block partials go to a __device__
// scratch array; the last block (ticket atomic) does the final reduce and
// resets the ticket so the kernel is graph-replay deterministic (the combine
// is order-independent: fixed-order tree over g_partials, not atomic floats).

#define EPS 1e-7f
#define MAX_BLOCKS 2048

__device__ float        g_partials[MAX_BLOCKS];
__device__ unsigned int g_ticket = 0;

__global__ __launch_bounds__(64, 1)
void iou_loss_kernel(const float4* __restrict__ pred,
                     const float4* __restrict__ targ,
                     float* __restrict__ out,
                     int n)
{
    const int i = blockIdx.x * blockDim.x + threadIdx.x;

    float v = 0.0f;
    if (i < n) {
        float4 a = __ldg(&pred[i]);   // cx, cy, w, h
        float4 b = __ldg(&targ[i]);

        float ax1 = a.x - a.z * 0.5f;
        float ay1 = a.y - a.w * 0.5f;
        float ax2 = a.x + a.z * 0.5f;
        float ay2 = a.y + a.w * 0.5f;

        float bx1 = b.x - b.z * 0.5f;
        float by1 = b.y - b.w * 0.5f;
        float bx2 = b.x + b.z * 0.5f;
        float by2 = b.y + b.w * 0.5f;

        float iw = fmaxf(fminf(ax2, bx2) - fmaxf(ax1, bx1), 0.0f);
        float ih = fmaxf(fminf(ay2, by2) - fmaxf(ay1, by1), 0.0f);
        float inter = iw * ih;

        float area1 = (ax2 - ax1) * (ay2 - ay1);
        float area2 = (bx2 - bx1) * (by2 - by1);
        float uni   = area1 + area2 - inter;

        v = 1.0f - inter / (uni + EPS);
    }

    // Intra-warp reduce.
    #pragma unroll
    for (int off = 16; off > 0; off >>= 1)
        v += __shfl_xor_sync(0xFFFFFFFFu, v, off);

    // Cross-warp reduce (2 warps).
    __shared__ float warp_sums[2];
    const int lane = threadIdx.x & 31;
    const int wid  = threadIdx.x >> 5;
    if (lane == 0) warp_sums[wid] = v;
    __syncthreads();

    __shared__ bool is_last;
    if (threadIdx.x == 0) {
        g_partials[blockIdx.x] = warp_sums[0] + warp_sums[1];
        __threadfence();
        unsigned int t = atomicAdd(&g_ticket, 1u);
        is_last = (t == gridDim.x - 1);
    }
    __syncthreads();

    // Last block to finish: reduce all block partials, write scalar, reset.
    if (is_last && wid == 0) {
        float s = 0.0f;
        for (int b = lane; b < (int)gridDim.x; b += 32)
            s += g_partials[b];
        #pragma unroll
        for (int off = 16; off > 0; off >>= 1)
            s += __shfl_xor_sync(0xFFFFFFFFu, s, off);
        if (lane == 0) {
            out[0] = s / (float)n;
            g_ticket = 0;   // reset for next graph replay
        }
    }
}

extern "C" void kernel_launch(void* const* d_in, const int* in_sizes, int n_in,
                              void* d_out, int out_size)
{
    const float4* pred = (const float4*)d_in[0];
    const float4* targ = (const float4*)d_in[1];
    float* out = (float*)d_out;

    int n = in_sizes[0] / 4;                    // 8192 boxes
    int blocks = (n + 63) / 64;                 // 128
    if (blocks > MAX_BLOCKS) blocks = MAX_BLOCKS;  // safety

    iou_loss_kernel<<<blocks, 64>>>(pred, targ, out, n);
}

// round 8
// speedup vs baseline: 1.3092x; 1.0386x over previous
#include <cuda_runtime.h>

// IoULoss: loss = mean_i ( 1 - IoU(pred_i, target_i) )   (diagonal-only, O(N))
// N = 8192 boxes, (N,4) f32 center-format [cx,cy,w,h]. Output: 1 f32 scalar.
//
// Shape: 64 CTAs x 128 threads = 8192 threads, one pair per thread, single
// wave. Cross-block combine: each block adds its partial (converted to Q32.32
// fixed point in double) into a u64 accumulator with integer atomicAdd —
// exact, order-independent, so the result is bit-deterministic across graph
// replays. A release-atomic ticket elects the last block; it acquires the sum
// with one ld.acquire.gpu, writes the scalar, and plain-stores the resets
// (kernel-completion ordering covers the next replay — no extra fences).

#define EPS 1e-7f
#define FP_SCALE 4294967296.0   // 2^32

__device__ unsigned long long g_sum = 0ull;
__device__ unsigned int       g_ticket = 0;

__global__ __launch_bounds__(128, 1)
void iou_loss_kernel(const float4* __restrict__ pred,
                     const float4* __restrict__ targ,
                     float* __restrict__ out,
                     int n)
{
    const int i = blockIdx.x * blockDim.x + threadIdx.x;

    float v = 0.0f;
    if (i < n) {
        float4 a = __ldg(&pred[i]);   // cx, cy, w, h
        float4 b = __ldg(&targ[i]);

        float ax1 = a.x - a.z * 0.5f;
        float ay1 = a.y - a.w * 0.5f;
        float ax2 = a.x + a.z * 0.5f;
        float ay2 = a.y + a.w * 0.5f;

        float bx1 = b.x - b.z * 0.5f;
        float by1 = b.y - b.w * 0.5f;
        float bx2 = b.x + b.z * 0.5f;
        float by2 = b.y + b.w * 0.5f;

        float iw = fmaxf(fminf(ax2, bx2) - fmaxf(ax1, bx1), 0.0f);
        float ih = fmaxf(fminf(ay2, by2) - fmaxf(ay1, by1), 0.0f);
        float inter = iw * ih;

        float area1 = (ax2 - ax1) * (ay2 - ay1);
        float area2 = (bx2 - bx1) * (by2 - by1);
        float uni   = area1 + area2 - inter;

        v = 1.0f - inter / (uni + EPS);
    }

    // Intra-warp reduce.
    #pragma unroll
    for (int off = 16; off > 0; off >>= 1)
        v += __shfl_xor_sync(0xFFFFFFFFu, v, off);

    // Cross-warp reduce (4 warps).
    __shared__ float warp_sums[4];
    const int lane = threadIdx.x & 31;
    const int wid  = threadIdx.x >> 5;
    if (lane == 0) warp_sums[wid] = v;
    __syncthreads();

    if (threadIdx.x == 0) {
        float bs = (warp_sums[0] + warp_sums[1]) + (warp_sums[2] + warp_sums[3]);

        // Exact, order-independent cross-block accumulation (Q32.32).
        long long q = llrint((double)bs * FP_SCALE);
        atomicAdd(&g_sum, (unsigned long long)q);

        // Release-atomic ticket: orders the sum-atomic before the increment.
        unsigned int t;
        asm volatile("atom.release.gpu.global.add.u32 %0, [%1], 1;"
                     : "=r"(t) : "l"(&g_ticket) : "memory");

        if (t == gridDim.x - 1) {
            // Acquire-load pairs with all blocks' release tickets.
            unsigned long long s;
            asm volatile("ld.acquire.gpu.global.u64 %0, [%1];"
                         : "=l"(s) : "l"(&g_sum) : "memory");
            out[0] = (float)((double)(long long)s / FP_SCALE / (double)n);
            // Resets: only the next graph replay reads these; kernel-completion
            // ordering makes them visible. Plain stores are sufficient.
            g_sum = 0ull;
            g_ticket = 0;
        }
    }
}

extern "C" void kernel_launch(void* const* d_in, const int* in_sizes, int n_in,
                              void* d_out, int out_size)
{
    const float4* pred = (const float4*)d_in[0];
    const float4* targ = (const float4*)d_in[1];
    float* out = (float*)d_out;

    int n = in_sizes[0] / 4;                     // 8192 boxes
    int blocks = (n + 127) / 128;                // 64

    iou_loss_kernel<<<blocks, 128>>>(pred, targ, out, n);
}